// round 5
// baseline (speedup 1.0000x reference)
#include <cuda_runtime.h>
#include <cstdint>

#define L_LEN   65536
#define L_MASK  (L_LEN - 1)
#define CIN     8
#define COUT    8
#define FS      4
#define TPB     128
#define TILE    512
#define ROWF    516                     // 512 + 4 halo floats, 16B-aligned stride
#define NTILES  (64 * (L_LEN / TILE))   // 8192
#define GRID    740                     // 5 blocks/SM * 148 SMs, single wave

// ---- packed f32x2 helpers (Blackwell sm_100a+) ------------------------------
__device__ __forceinline__ float2 ffma2(float2 a, float2 b, float2 c) {
    float2 d;
    asm("fma.rn.f32x2 %0, %1, %2, %3;"
        : "=l"(reinterpret_cast<unsigned long long&>(d))
        : "l"(reinterpret_cast<const unsigned long long&>(a)),
          "l"(reinterpret_cast<const unsigned long long&>(b)),
          "l"(reinterpret_cast<const unsigned long long&>(c)));
    return d;
}

__device__ __forceinline__ float2 dup2(float x) {
    float2 d;
    asm("mov.b64 %0, {%1, %1};"
        : "=l"(reinterpret_cast<unsigned long long&>(d))
        : "f"(x));
    return d;
}

__device__ __forceinline__ uint32_t smem_u32(const void* p) {
    uint32_t a;
    asm("{ .reg .u64 t; cvta.to.shared.u64 t, %1; cvt.u32.u64 %0, t; }"
        : "=r"(a) : "l"(p));
    return a;
}

__device__ __forceinline__ void cp_async16(uint32_t dst, const float* src) {
    asm volatile("cp.async.cg.shared.global [%0], [%1], 16;"
                 :: "r"(dst), "l"(src));
}

// ----------------------------------------------------------------------------
// out[b, co, l] = bias[co] + sum_{ci,k} x[b, ci, (l+k) mod L] * W[co, ci, k]
//
// Persistent blocks, block-cyclic over 8192 tiles of 512 positions.
// Double-buffered SMEM x tiles filled by cp.async: tile n+1 loads overlap
// tile n compute, so DRAM latency is never exposed after the prologue.
// Thread t owns positions [4t, 4t+4): conflict-free LDS.128 windows and
// perfectly coalesced STG.128 stores. All 8 co as 4 f32x2-packed pairs.
// ----------------------------------------------------------------------------
__global__ __launch_bounds__(TPB, 5)
void conv_pbc_kernel(const float* __restrict__ x,
                     const float* __restrict__ W,
                     const float* __restrict__ bias,
                     float* __restrict__ out)
{
    __shared__ float  xs[2][CIN][ROWF];
    __shared__ float2 w2s[CIN][FS][COUT / 2];   // (W[2cp,ci,k], W[2cp+1,ci,k])
    __shared__ float2 b2s[COUT / 2];

    const int t = threadIdx.x;

    // weights / bias into SMEM (128 packed entries, one per thread);
    // visibility to compute guaranteed by the first in-loop __syncthreads().
    {
        const int cp = t & 3;
        const int k  = (t >> 2) & 3;
        const int ci = (t >> 4) & 7;
        w2s[ci][k][cp] = make_float2(W[(2 * cp)     * CIN * FS + ci * FS + k],
                                     W[(2 * cp + 1) * CIN * FS + ci * FS + k]);
    }
    if (t < COUT / 2)
        b2s[t] = make_float2(bias[2 * t], bias[2 * t + 1]);

    const uint32_t xs_base = smem_u32(&xs[0][0][0]);

    // issue all cp.asyncs for one tile into buffer `buf`
    auto issue_tile = [&](int tile, int buf) {
        const int b    = tile >> 7;            // 128 tiles per batch
        const int base = (tile & 127) << 9;    // tile * 512
        const float* __restrict__ xb = x + (size_t)b * CIN * L_LEN;
        const uint32_t dst0 = xs_base + (uint32_t)buf * (CIN * ROWF * 4) + 16u * t;
        #pragma unroll
        for (int ci = 0; ci < CIN; ++ci)
            cp_async16(dst0 + ci * (ROWF * 4),
                       xb + (size_t)ci * L_LEN + base + 4 * t);
        if (t < CIN)   // halo: next 4 floats, circular (always 16B aligned)
            cp_async16(xs_base + (uint32_t)buf * (CIN * ROWF * 4)
                               + t * (ROWF * 4) + TILE * 4,
                       xb + (size_t)t * L_LEN + ((base + TILE) & L_MASK));
    };

    const int tile0 = blockIdx.x;
    issue_tile(tile0, 0);
    asm volatile("cp.async.commit_group;");

    int it = 0;
    for (int tile = tile0; tile < NTILES; tile += GRID, ++it) {
        const int buf = it & 1;

        if (tile + GRID < NTILES)
            issue_tile(tile + GRID, buf ^ 1);
        asm volatile("cp.async.commit_group;");
        asm volatile("cp.async.wait_group 1;");
        __syncthreads();                       // tile `tile` resident in xs[buf]

        // ---- compute: 4 positions x 8 co from SMEM ----
        float2 acc[4][COUT / 2];
        {
            const float2 c0 = b2s[0], c1 = b2s[1], c2 = b2s[2], c3 = b2s[3];
            #pragma unroll
            for (int q = 0; q < 4; ++q) {
                acc[q][0] = c0; acc[q][1] = c1; acc[q][2] = c2; acc[q][3] = c3;
            }
        }

        #pragma unroll
        for (int ci = 0; ci < CIN; ++ci) {
            float2 wv[FS][COUT / 2];
            #pragma unroll
            for (int k = 0; k < FS; ++k)
                #pragma unroll
                for (int cp = 0; cp < 4; ++cp)
                    wv[k][cp] = w2s[ci][k][cp];

            float xw[8];
            {
                const float4 a0 = *reinterpret_cast<const float4*>(&xs[buf][ci][4 * t]);
                const float4 a1 = *reinterpret_cast<const float4*>(&xs[buf][ci][4 * t + 4]);
                xw[0] = a0.x; xw[1] = a0.y; xw[2] = a0.z; xw[3] = a0.w;
                xw[4] = a1.x; xw[5] = a1.y; xw[6] = a1.z; xw[7] = a1.w;
            }

            #pragma unroll
            for (int i = 0; i < 7; ++i) {
                const float2 xk = dup2(xw[i]);
                #pragma unroll
                for (int k = 0; k < FS; ++k) {
                    const int q = i - k;
                    if (q >= 0 && q < 4) {
                        #pragma unroll
                        for (int cp = 0; cp < 4; ++cp)
                            acc[q][cp] = ffma2(wv[k][cp], xk, acc[q][cp]);
                    }
                }
            }
        }

        // ---- coalesced STG.128 epilogue ----
        {
            const int b    = tile >> 7;
            const int base = (tile & 127) << 9;
            float* __restrict__ ob = out + (size_t)b * COUT * L_LEN + base + 4 * t;
            #pragma unroll
            for (int cp = 0; cp < 4; ++cp) {
                float4 v;
                v.x = acc[0][cp].x; v.y = acc[1][cp].x;
                v.z = acc[2][cp].x; v.w = acc[3][cp].x;
                *reinterpret_cast<float4*>(ob + (size_t)(2 * cp) * L_LEN) = v;
                v.x = acc[0][cp].y; v.y = acc[1][cp].y;
                v.z = acc[2][cp].y; v.w = acc[3][cp].y;
                *reinterpret_cast<float4*>(ob + (size_t)(2 * cp + 1) * L_LEN) = v;
            }
        }

        __syncthreads();   // all reads of xs[buf] done before it is refilled
    }
}

extern "C" void kernel_launch(void* const* d_in, const int* in_sizes, int n_in,
                              void* d_out, int out_size)
{
    const float* x    = (const float*)d_in[0];  // (64, 8, 65536)
    const float* W    = (const float*)d_in[1];  // (8, 8, 4)
    const float* bias = (const float*)d_in[2];  // (8,)
    float* out        = (float*)d_out;          // (64, 8, 65536)

    conv_pbc_kernel<<<GRID, TPB>>>(x, W, bias, out);
}

// round 6
// speedup vs baseline: 1.1200x; 1.1200x over previous
#include <cuda_runtime.h>
#include <cstdint>

#define L_LEN   65536
#define L_MASK  (L_LEN - 1)
#define CIN     8
#define COUT    8
#define FS      4
#define TPB     128
#define TILE    512
#define ROWF    516        // 512 + 4 halo floats, 16B-aligned row stride

// ---- packed f32x2 helpers (Blackwell sm_100a+) ------------------------------
__device__ __forceinline__ float2 ffma2(float2 a, float2 b, float2 c) {
    float2 d;
    asm("fma.rn.f32x2 %0, %1, %2, %3;"
        : "=l"(reinterpret_cast<unsigned long long&>(d))
        : "l"(reinterpret_cast<const unsigned long long&>(a)),
          "l"(reinterpret_cast<const unsigned long long&>(b)),
          "l"(reinterpret_cast<const unsigned long long&>(c)));
    return d;
}

__device__ __forceinline__ float2 dup2(float x) {
    float2 d;
    asm("mov.b64 %0, {%1, %1};"
        : "=l"(reinterpret_cast<unsigned long long&>(d))
        : "f"(x));
    return d;
}

__device__ __forceinline__ uint32_t smem_u32(const void* p) {
    uint32_t a;
    asm("{ .reg .u64 t; cvta.to.shared.u64 t, %1; cvt.u32.u64 %0, t; }"
        : "=r"(a) : "l"(p));
    return a;
}

__device__ __forceinline__ void cp_async16(uint32_t dst, const float* src) {
    asm volatile("cp.async.cg.shared.global [%0], [%1], 16;"
                 :: "r"(dst), "l"(src));
}

// ----------------------------------------------------------------------------
// out[b, co, l] = bias[co] + sum_{ci,k} x[b, ci, (l+k) mod L] * W[co, ci, k]
//
// Block: two adjacent 512-position tiles of one batch, 2-deep cp.async
// pipeline: both tile loads are issued up front; tile1's DRAM latency is
// hidden behind tile0's compute. Thread t owns positions [4t, 4t+4):
// conflict-free LDS.128 windows, coalesced STG.128, all 8 co as f32x2 pairs.
// ----------------------------------------------------------------------------
__global__ __launch_bounds__(TPB, 6)
void conv_pbc_kernel(const float* __restrict__ x,
                     const float* __restrict__ W,
                     const float* __restrict__ bias,
                     float* __restrict__ out)
{
    __shared__ float  xs[2][CIN][ROWF];
    __shared__ float2 w2s[CIN][FS][COUT / 2];   // (W[2cp,ci,k], W[2cp+1,ci,k])
    __shared__ float2 b2s[COUT / 2];

    const int t = threadIdx.x;

    // weights / bias into SMEM (128 packed entries, one per thread);
    // visible to compute after the first __syncthreads below.
    {
        const int cp = t & 3;
        const int k  = (t >> 2) & 3;
        const int ci = (t >> 4) & 7;
        w2s[ci][k][cp] = make_float2(W[(2 * cp)     * CIN * FS + ci * FS + k],
                                     W[(2 * cp + 1) * CIN * FS + ci * FS + k]);
    }
    if (t < COUT / 2)
        b2s[t] = make_float2(bias[2 * t], bias[2 * t + 1]);

    const int b     = blockIdx.x >> 6;           // 64 tile-pairs per batch
    const int base0 = (blockIdx.x & 63) << 10;   // pair start (2 * 512)

    const float* __restrict__ xb = x   + (size_t)b * CIN  * L_LEN;
    float*       __restrict__ ob = out + (size_t)b * COUT * L_LEN;

    const uint32_t xs_base = smem_u32(&xs[0][0][0]);

    // issue all cp.asyncs for the tile starting at base0 + 512*half
    auto issue_tile = [&](int half) {
        const int base = base0 + TILE * half;
        const uint32_t dst0 =
            xs_base + (uint32_t)half * (CIN * ROWF * 4) + 16u * t;
        #pragma unroll
        for (int ci = 0; ci < CIN; ++ci)
            cp_async16(dst0 + ci * (ROWF * 4),
                       xb + (size_t)ci * L_LEN + base + 4 * t);
        if (t < CIN)   // halo: next 4 floats, circular (always 16B aligned)
            cp_async16(xs_base + (uint32_t)half * (CIN * ROWF * 4)
                               + t * (ROWF * 4) + TILE * 4,
                       xb + (size_t)t * L_LEN + ((base + TILE) & L_MASK));
    };

    // compute + store one resident tile
    auto do_tile = [&](int half) {
        const int base = base0 + TILE * half;

        float2 acc[4][COUT / 2];
        {
            const float2 c0 = b2s[0], c1 = b2s[1], c2 = b2s[2], c3 = b2s[3];
            #pragma unroll
            for (int q = 0; q < 4; ++q) {
                acc[q][0] = c0; acc[q][1] = c1; acc[q][2] = c2; acc[q][3] = c3;
            }
        }

        #pragma unroll
        for (int ci = 0; ci < CIN; ++ci) {
            float2 wv[FS][COUT / 2];
            #pragma unroll
            for (int k = 0; k < FS; ++k)
                #pragma unroll
                for (int cp = 0; cp < 4; ++cp)
                    wv[k][cp] = w2s[ci][k][cp];

            float xw[8];
            {
                const float4 a0 =
                    *reinterpret_cast<const float4*>(&xs[half][ci][4 * t]);
                const float4 a1 =
                    *reinterpret_cast<const float4*>(&xs[half][ci][4 * t + 4]);
                xw[0] = a0.x; xw[1] = a0.y; xw[2] = a0.z; xw[3] = a0.w;
                xw[4] = a1.x; xw[5] = a1.y; xw[6] = a1.z; xw[7] = a1.w;
            }

            #pragma unroll
            for (int i = 0; i < 7; ++i) {
                const float2 xk = dup2(xw[i]);
                #pragma unroll
                for (int k = 0; k < FS; ++k) {
                    const int q = i - k;
                    if (q >= 0 && q < 4) {
                        #pragma unroll
                        for (int cp = 0; cp < 4; ++cp)
                            acc[q][cp] = ffma2(wv[k][cp], xk, acc[q][cp]);
                    }
                }
            }
        }

        float* __restrict__ op = ob + base + 4 * t;
        #pragma unroll
        for (int cp = 0; cp < 4; ++cp) {
            float4 v;
            v.x = acc[0][cp].x; v.y = acc[1][cp].x;
            v.z = acc[2][cp].x; v.w = acc[3][cp].x;
            *reinterpret_cast<float4*>(op + (size_t)(2 * cp) * L_LEN) = v;
            v.x = acc[0][cp].y; v.y = acc[1][cp].y;
            v.z = acc[2][cp].y; v.w = acc[3][cp].y;
            *reinterpret_cast<float4*>(op + (size_t)(2 * cp + 1) * L_LEN) = v;
        }
    };

    // 2-deep pipeline: tile1's loads fly while tile0 computes
    issue_tile(0);
    asm volatile("cp.async.commit_group;");
    issue_tile(1);
    asm volatile("cp.async.commit_group;");

    asm volatile("cp.async.wait_group 1;");
    __syncthreads();          // tile0 resident (+ weights visible)
    do_tile(0);

    asm volatile("cp.async.wait_group 0;");
    __syncthreads();          // tile1 resident
    do_tile(1);
}

extern "C" void kernel_launch(void* const* d_in, const int* in_sizes, int n_in,
                              void* d_out, int out_size)
{
    const float* x    = (const float*)d_in[0];  // (64, 8, 65536)
    const float* W    = (const float*)d_in[1];  // (8, 8, 4)
    const float* bias = (const float*)d_in[2];  // (8,)
    float* out        = (float*)d_out;          // (64, 8, 65536)

    // 64 batches * 64 tile-pairs = 4096 blocks of 128 threads
    conv_pbc_kernel<<<64 * (L_LEN / (2 * TILE)), TPB>>>(x, W, bias, out);
}